// round 10
// baseline (speedup 1.0000x reference)
#include <cuda_runtime.h>

#define H      128
#define STEPS  65536
#define NBLK   27

// Cross-stage activations (device globals; no allocation)
__device__ __align__(16) float g_h[3][H];     // finished LSTM hidden per layer
__device__ __align__(16) float g_fc[400];
__device__ __align__(16) float g_l1[512];     // 500 used
// flags[stage][slot*32], 64 slots x 128B lines per stage.
// stages 0-2: LSTM layer done; 3: FC done; 4: L1 done.
// Zero at load; reset in-kernel by the L2 block each launch.
__device__ int g_flag[5][64 * 32];

__device__ __forceinline__ float tanh_fast(float x) {
    float y; asm("tanh.approx.f32 %0, %1;" : "=f"(y) : "f"(x)); return y;
}
__device__ __forceinline__ float sig_fast(float x) {
    return 0.5f * tanh_fast(0.5f * x) + 0.5f;
}
__device__ __forceinline__ float dot4(float4 a, float4 b) {
    return a.x * b.x + a.y * b.y + a.z * b.z + a.w * b.w;
}
__device__ __forceinline__ int ld_acquire(const int* p) {
    int v;
    asm volatile("ld.acquire.gpu.global.b32 %0, [%1];" : "=r"(v) : "l"(p) : "memory");
    return v;
}
__device__ __forceinline__ void red_release(int* p, int v) {
    asm volatile("red.release.gpu.global.add.s32 [%0], %1;" :: "l"(p), "r"(v) : "memory");
}
__device__ __forceinline__ void fence_gpu() {
    asm volatile("fence.acq_rel.gpu;" ::: "memory");
}
// Per-warp wait: lane 0 polls with acquire; syncwarp orders the rest.
__device__ __forceinline__ void warp_wait(int* p, int tgt) {
    if ((threadIdx.x & 31) == 0) {
        while (ld_acquire(p) < tgt) { }
    }
    __syncwarp();
}
// interleaved full-warp sum reduce of N accumulators -> lane 0
template <int N>
__device__ __forceinline__ void warp_sumN(float* s) {
#pragma unroll
    for (int off = 16; off > 0; off >>= 1)
#pragma unroll
        for (int k = 0; k < N; ++k)
            s[k] += __shfl_down_sync(0xFFFFFFFFu, s[k], off);
}

__global__ __launch_bounds__(512, 1)
void fused_rnn(const float* __restrict__ inputs,
               const float* __restrict__ W_ih,
               const float* __restrict__ b_ih,
               const float* __restrict__ b_hh,
               const float* __restrict__ W_fc,
               const float* __restrict__ b_fc,
               const float* __restrict__ W_l1,
               const float* __restrict__ b_l1,
               const float* __restrict__ W_l2,
               const float* __restrict__ b_l2,
               float* __restrict__ out)
{
    __shared__ float sgate[96];                  // LSTM gate exchange
    const int b    = blockIdx.x;
    const int t    = threadIdx.x;
    const int wid  = t >> 5;
    const int lane = t & 31;

    // ============ LSTM: blocks 0-11 (layer = b>>2, 4 blocks/layer) ============
    // Block `sub` owns h[sub*32 .. sub*32+32). It computes the i, g, o gate
    // rows for those outputs (f dead: c0=0): 96 rows. Warp `wid` owns local
    // rows wid + k*16 (k=0..5). One COALESCED warp-LDG.128 per row
    // (lane = float4 column) -> 4 wavefronts/row instead of 32.
    if (b < 12) {
        const int layer = b >> 2, sub = b & 3;

        float4 w[6]; float bias[6];
#pragma unroll
        for (int k = 0; k < 6; ++k) {
            const int lr = wid + k * 16;            // 0..95
            const int gs = (lr < 32) ? 0 : (lr < 64) ? 256 : 384;
            const int row = gs + sub * 32 + (lr & 31);
            w[k] = reinterpret_cast<const float4*>(
                       W_ih + ((size_t)layer * 512 + row) * H)[lane];
            bias[k] = b_ih[layer * 512 + row] + b_hh[layer * 512 + row];
        }

        float4 x;
        if (layer == 0) {
            x = reinterpret_cast<const float4*>(
                    inputs + (size_t)(STEPS - 1) * H)[lane];
        } else {
            warp_wait(&g_flag[layer - 1][(sub * 16 + wid) * 32], 4);
            x = reinterpret_cast<const float4*>(g_h[layer - 1])[lane];
        }

        float s[6];
#pragma unroll
        for (int k = 0; k < 6; ++k) s[k] = dot4(w[k], x);
        warp_sumN<6>(s);
        if (lane == 0)
#pragma unroll
            for (int k = 0; k < 6; ++k) sgate[wid + k * 16] = s[k] + bias[k];
        __syncthreads();

        if (wid == 0) {                          // warp 0: activation + publish
            float ig = sgate[lane], gg = sgate[32 + lane], og = sgate[64 + lane];
            float c  = sig_fast(ig) * tanh_fast(gg);
            g_h[layer][sub * 32 + lane] = sig_fast(og) * tanh_fast(c);
            __syncwarp();
            fence_gpu();                          // order ALL h stores before flags
            red_release(&g_flag[layer][lane * 32], 1);
            red_release(&g_flag[layer][(lane + 32) * 32], 1);
        }
        return;
    }

    // ============ FC 400x128: blocks 12-15 (100 rows, rows wid+k*16) ============
    if (b < 16) {
        const int sub = b - 12;

        float4 w[7]; float bias[7];
#pragma unroll
        for (int k = 0; k < 7; ++k) {
            const int lr = wid + k * 16;
            if (lr < 100) {
                const int row = sub * 100 + lr;
                w[k] = reinterpret_cast<const float4*>(W_fc + (size_t)row * H)[lane];
                bias[k] = b_fc[row];
            }
        }

        warp_wait(&g_flag[2][(sub * 16 + wid) * 32], 4);
        const float4 x = reinterpret_cast<const float4*>(g_h[2])[lane];

        float s[7];
#pragma unroll
        for (int k = 0; k < 7; ++k)
            s[k] = (wid + k * 16 < 100) ? dot4(w[k], x) : 0.0f;
        warp_sumN<7>(s);
        if (lane == 0)
#pragma unroll
            for (int k = 0; k < 7; ++k) {
                const int lr = wid + k * 16;
                if (lr < 100) g_fc[sub * 100 + lr] = s[k] + bias[k];
            }

        __syncthreads();
        if (wid == 0) {
            fence_gpu();
            red_release(&g_flag[3][lane * 32], 1);
            red_release(&g_flag[3][(lane + 32) * 32], 1);
        }
        return;
    }

    // ============ L1 500x400: blocks 16-25 (50 rows, rows wid+k*16) ============
    if (b < 26) {
        const int sub = b - 16;

        // k=0..2 always active (lr<=47); k=3 only wid<2 (lr=48,49).
        float4 w[4][4]; float bias[4];
        const bool r3 = (wid < 2);
#pragma unroll
        for (int k = 0; k < 4; ++k) {
            const int lr = wid + k * 16;
            if (k < 3 || r3) {
                const int row = sub * 50 + lr;
                const float4* wr = reinterpret_cast<const float4*>(
                    W_l1 + (size_t)row * 400);
                w[k][0] = wr[lane];
                w[k][1] = wr[lane + 32];
                w[k][2] = wr[lane + 64];
                if (lane < 4) w[k][3] = wr[lane + 96];
                bias[k] = b_l1[row];
            }
        }

        warp_wait(&g_flag[3][((sub * 16 + wid) & 63) * 32], 4);
        const float4* xf = reinterpret_cast<const float4*>(g_fc);
        float4 x0 = xf[lane], x1 = xf[lane + 32], x2 = xf[lane + 64];
        float4 x3; if (lane < 4) x3 = xf[lane + 96];

        float s[4];
#pragma unroll
        for (int k = 0; k < 4; ++k) {
            float v = 0.0f;
            if (k < 3 || r3) {
                v = dot4(w[k][0], x0) + dot4(w[k][1], x1) + dot4(w[k][2], x2);
                if (lane < 4) v += dot4(w[k][3], x3);
            }
            s[k] = v;
        }
        warp_sumN<4>(s);
        if (lane == 0) {
#pragma unroll
            for (int k = 0; k < 3; ++k)
                g_l1[sub * 50 + wid + k * 16] = s[k] + bias[k];
            if (r3) g_l1[sub * 50 + wid + 48] = s[3] + bias[3];
        }

        __syncthreads();
        if (wid == 0) {
            fence_gpu();
            red_release(&g_flag[4][lane * 32], 1);
            red_release(&g_flag[4][(lane + 32) * 32], 1);
        }
        return;
    }

    // ============ L2 63x500: block 26 (rows wid+k*16) + flag reset ============
    {
        // k=0..2 always active; k=3 only wid<15 (lr=48..62).
        float4 w[4][4]; float bias[4];
        const bool r3 = (wid < 15);
#pragma unroll
        for (int k = 0; k < 4; ++k) {
            const int lr = wid + k * 16;
            if (k < 3 || r3) {
                const float4* wr = reinterpret_cast<const float4*>(
                    W_l2 + (size_t)lr * 500);
                w[k][0] = wr[lane];
                w[k][1] = wr[lane + 32];
                w[k][2] = wr[lane + 64];
                if (lane < 29) w[k][3] = wr[lane + 96];   // 125 float4 per row
                bias[k] = b_l2[lr];
            }
        }

        warp_wait(&g_flag[4][wid * 32], 10);
        const float4* xf = reinterpret_cast<const float4*>(g_l1);
        float4 x0 = xf[lane], x1 = xf[lane + 32], x2 = xf[lane + 64];
        float4 x3; if (lane < 29) x3 = xf[lane + 96];

        float s[4];
#pragma unroll
        for (int k = 0; k < 4; ++k) {
            float v = 0.0f;
            if (k < 3 || r3) {
                v = dot4(w[k][0], x0) + dot4(w[k][1], x1) + dot4(w[k][2], x2);
                if (lane < 29) v += dot4(w[k][3], x3);
            }
            s[k] = v;
        }
        warp_sumN<4>(s);
        if (lane == 0) {
#pragma unroll
            for (int k = 0; k < 3; ++k)
                out[wid + k * 16] = s[k] + bias[k];
            if (r3) out[wid + 48] = s[3] + bias[3];
        }

        // Reset flags for the next graph replay. Safe: all 16 of this block's
        // warp-waits passing implies (transitively, through the release/acquire
        // chain) every flag write in this launch has landed and no block will
        // read flags again.
        __syncthreads();
        if (t < 320)
            *(volatile int*)&g_flag[t >> 6][(t & 63) * 32] = 0;
    }
}

extern "C" void kernel_launch(void* const* d_in, const int* in_sizes, int n_in,
                              void* d_out, int out_size) {
    const float* inputs = (const float*)d_in[0];
    const float* W_ih   = (const float*)d_in[1];
    // d_in[2] = W_hh — dead (h0 = 0)
    const float* b_ih   = (const float*)d_in[3];
    const float* b_hh   = (const float*)d_in[4];
    const float* W_fc   = (const float*)d_in[5];
    const float* b_fc   = (const float*)d_in[6];
    const float* W_l1   = (const float*)d_in[7];
    const float* b_l1   = (const float*)d_in[8];
    const float* W_l2   = (const float*)d_in[9];
    const float* b_l2   = (const float*)d_in[10];
    float* out = (float*)d_out;

    fused_rnn<<<NBLK, 512>>>(inputs, W_ih, b_ih, b_hh,
                             W_fc, b_fc, W_l1, b_l1, W_l2, b_l2, out);
}

// round 11
// speedup vs baseline: 1.9348x; 1.9348x over previous
#include <cuda_runtime.h>
#include <cstdint>

#define H      128
#define STEPS  65536
#define NC     8          // cluster = whole grid

__device__ __forceinline__ float tanh_fast(float x) {
    float y; asm("tanh.approx.f32 %0, %1;" : "=f"(y) : "f"(x)); return y;
}
__device__ __forceinline__ float sig_fast(float x) {
    return 0.5f * tanh_fast(0.5f * x) + 0.5f;
}
__device__ __forceinline__ float dot4(float4 a, float4 b) {
    return a.x * b.x + a.y * b.y + a.z * b.z + a.w * b.w;
}
__device__ __forceinline__ uint32_t smem_u32(const void* p) {
    uint32_t a;
    asm("{ .reg .u64 t; cvta.to.shared.u64 t, %1; cvt.u32.u64 %0, t; }"
        : "=r"(a) : "l"(p));
    return a;
}
__device__ __forceinline__ uint32_t mapa_u32(uint32_t a, uint32_t rank) {
    uint32_t r;
    asm("mapa.shared::cluster.u32 %0, %1, %2;" : "=r"(r) : "r"(a), "r"(rank));
    return r;
}
__device__ __forceinline__ void st_cluster_f32(uint32_t addr, float v) {
    asm volatile("st.shared::cluster.b32 [%0], %1;"
                 :: "r"(addr), "r"(__float_as_uint(v)) : "memory");
}
__device__ __forceinline__ void cluster_sync() {
    asm volatile("barrier.cluster.arrive.aligned;" ::: "memory");
    asm volatile("barrier.cluster.wait.aligned;"   ::: "memory");
}
#define CP_ASYNC16(dst, src) \
    asm volatile("cp.async.cg.shared.global [%0], [%1], 16;" \
                 :: "r"(dst), "l"(src) : "memory")
#define CP_COMMIT()  asm volatile("cp.async.commit_group;" ::: "memory")
#define CP_WAIT0()   asm volatile("cp.async.wait_group 0;" ::: "memory")

template <int N>
__device__ __forceinline__ void warp_sumN(float* s) {
#pragma unroll
    for (int off = 16; off > 0; off >>= 1)
#pragma unroll
        for (int k = 0; k < N; ++k)
            s[k] += __shfl_down_sync(0xFFFFFFFFu, s[k], off);
}

// Dynamic smem layout (floats):
//   buf0[512] | buf1[512] | gA[384] | gB[384] | wl1[64 rows * 400]
#define OFF_BUF0  0
#define OFF_BUF1  512
#define OFF_GA    1024
#define OFF_GB    1408
#define OFF_WL1   1792
#define SMEM_FLOATS (1792 + 64 * 400)

extern __shared__ float sm[];

__global__ void __launch_bounds__(512, 1) __cluster_dims__(NC, 1, 1)
fused_rnn(const float* __restrict__ inputs,
          const float* __restrict__ W_ih,
          const float* __restrict__ b_ih,
          const float* __restrict__ b_hh,
          const float* __restrict__ W_fc,
          const float* __restrict__ b_fc,
          const float* __restrict__ W_l1,
          const float* __restrict__ b_l1,
          const float* __restrict__ W_l2,
          const float* __restrict__ b_l2,
          float* __restrict__ out)
{
    const int t    = threadIdx.x;
    const int wid  = t >> 5;
    const int lane = t & 31;
    uint32_t rank;
    asm("mov.u32 %0, %%cluster_ctarank;" : "=r"(rank));
    const int g = (int)rank * 16 + wid;        // global warp id, 0..127

    float* buf0 = sm + OFF_BUF0;
    float* buf1 = sm + OFF_BUF1;
    float* gbuf[2] = { sm + OFF_GA, sm + OFF_GB };
    float* wl1s = sm + OFF_WL1;

    // ---------- x0: last-timestep input (every CTA, warp 0) ----------
    if (t < 32)
        reinterpret_cast<float4*>(buf1)[t] =
            reinterpret_cast<const float4*>(inputs + (size_t)(STEPS - 1) * H)[t];

    // ---------- weight prefetch: LSTM (regs) ----------
    // warp g owns rows r = g + 128k (k=0..2) of each layer's [i|g|o] block.
    float4 wl[3][3]; float bl[3][3];
#pragma unroll
    for (int l = 0; l < 3; ++l)
#pragma unroll
        for (int k = 0; k < 3; ++k) {
            const int r = g + 128 * k;              // 0..383
            const int j = r & 127;
            const int grow = (r < 128) ? j : (r < 256) ? 256 + j : 384 + j;
            wl[l][k] = reinterpret_cast<const float4*>(
                           W_ih + ((size_t)l * 512 + grow) * H)[lane];
            bl[l][k] = b_ih[l * 512 + grow] + b_hh[l * 512 + grow];
        }

    // ---------- FC (regs): rows r = g + 128k, r < 400 ----------
    float4 wfc[4]; float bfc[4];
#pragma unroll
    for (int k = 0; k < 4; ++k) {
        const int r = g + 128 * k;
        if (r < 400) {
            wfc[k] = reinterpret_cast<const float4*>(W_fc + (size_t)r * H)[lane];
            bfc[k] = b_fc[r];
        }
    }

    // ---------- L2 (regs): row g (g < 63), 125 float4 ----------
    float4 w2[4]; float b2 = 0.0f;
    if (g < 63) {
        const float4* wr = reinterpret_cast<const float4*>(W_l2 + (size_t)g * 500);
        w2[0] = wr[lane]; w2[1] = wr[lane + 32]; w2[2] = wr[lane + 64];
        if (lane < 29) w2[3] = wr[lane + 96];
        b2 = b_l2[g];
    }

    // ---------- L1 (cp.async -> smem): rows r = g + 128k, r < 500 ----------
    float bl1[4];
#pragma unroll
    for (int k = 0; k < 4; ++k) {
        const int r = g + 128 * k;
        if (r < 500) {
            const float* src = W_l1 + (size_t)r * 400;
            uint32_t dst = smem_u32(wl1s + (wid * 4 + k) * 400);
            CP_ASYNC16(dst + 16 * lane,        src + 4 * lane);
            CP_ASYNC16(dst + 16 * (lane + 32), src + 4 * (lane + 32));
            CP_ASYNC16(dst + 16 * (lane + 64), src + 4 * (lane + 64));
            if (lane < 4)
                CP_ASYNC16(dst + 16 * (lane + 96), src + 4 * (lane + 96));
            bl1[k] = b_l1[r];
        }
    }
    CP_COMMIT();

    __syncthreads();    // x0 visible CTA-wide

    // ================= LSTM layers 0-2 =================
    // inputs:  l=0: buf1 (x0), l=1: buf0 (h1), l=2: buf1 (h2)
    // gates -> gbuf[l&1] (remote fan-out); h -> {buf0, buf1, buf0}
#pragma unroll
    for (int l = 0; l < 3; ++l) {
        float* xb = (l == 1) ? buf0 : buf1;
        float* gl = gbuf[l & 1];
        float* hb = (l == 1) ? buf1 : buf0;

        const float4 x = reinterpret_cast<const float4*>(xb)[lane];
        float s[3];
#pragma unroll
        for (int k = 0; k < 3; ++k) s[k] = dot4(wl[l][k], x);
        warp_sumN<3>(s);

        const float v0 = __shfl_sync(0xFFFFFFFFu, s[0], 0);
        const float v1 = __shfl_sync(0xFFFFFFFFu, s[1], 0);
        const float v2 = __shfl_sync(0xFFFFFFFFu, s[2], 0);
        const int sel = lane >> 3, tgt = lane & 7;    // lanes 0-23: 3 rows x 8 CTAs
        if (sel < 3) {
            const float v = (sel == 0 ? v0 : sel == 1 ? v1 : v2) + bl[l][sel];
            st_cluster_f32(mapa_u32(smem_u32(&gl[g + 128 * sel]), tgt), v);
        }

        cluster_sync();                      // release stores / acquire reads

        if (t < 128) {                        // local activation (all CTAs)
            float ig = gl[t], gc = gl[128 + t], og = gl[256 + t];
            float c = sig_fast(ig) * tanh_fast(gc);
            hb[t] = sig_fast(og) * tanh_fast(c);
        }
        __syncthreads();
    }

    // ================= FC 400x128: in buf0 (h3), out buf1 =================
    {
        const float4 x = reinterpret_cast<const float4*>(buf0)[lane];
        float s[4];
#pragma unroll
        for (int k = 0; k < 4; ++k)
            s[k] = (g + 128 * k < 400) ? dot4(wfc[k], x) : 0.0f;
        warp_sumN<4>(s);
        const float v0 = __shfl_sync(0xFFFFFFFFu, s[0], 0);
        const float v1 = __shfl_sync(0xFFFFFFFFu, s[1], 0);
        const float v2 = __shfl_sync(0xFFFFFFFFu, s[2], 0);
        const float v3 = __shfl_sync(0xFFFFFFFFu, s[3], 0);
        const int sel = lane >> 3, tgt = lane & 7;
        const int r = g + 128 * sel;
        if (r < 400) {
            const float v = (sel == 0 ? v0 : sel == 1 ? v1 : sel == 2 ? v2 : v3)
                            + bfc[sel];
            st_cluster_f32(mapa_u32(smem_u32(&buf1[r]), tgt), v);
        }
        cluster_sync();
    }

    // ================= L1 500x400: in buf1, weights smem, out buf0 =================
    {
        CP_WAIT0();
        __syncthreads();                      // all lanes' cp.async rows complete

        const float4* xf = reinterpret_cast<const float4*>(buf1);
        const float4 x0 = xf[lane], x1 = xf[lane + 32], x2 = xf[lane + 64];
        float4 x3 = make_float4(0.f, 0.f, 0.f, 0.f);
        if (lane < 4) x3 = xf[lane + 96];

        float s[4];
#pragma unroll
        for (int k = 0; k < 4; ++k) {
            float v = 0.0f;
            if (g + 128 * k < 500) {
                const float4* wr = reinterpret_cast<const float4*>(
                    wl1s + (wid * 4 + k) * 400);
                v = dot4(wr[lane], x0) + dot4(wr[lane + 32], x1)
                  + dot4(wr[lane + 64], x2);
                if (lane < 4) v += dot4(wr[lane + 96], x3);
            }
            s[k] = v;
        }
        warp_sumN<4>(s);
        const float v0 = __shfl_sync(0xFFFFFFFFu, s[0], 0);
        const float v1 = __shfl_sync(0xFFFFFFFFu, s[1], 0);
        const float v2 = __shfl_sync(0xFFFFFFFFu, s[2], 0);
        const float v3 = __shfl_sync(0xFFFFFFFFu, s[3], 0);
        const int sel = lane >> 3, tgt = lane & 7;
        const int r = g + 128 * sel;
        if (r < 500) {
            const float v = (sel == 0 ? v0 : sel == 1 ? v1 : sel == 2 ? v2 : v3)
                            + bl1[sel];
            st_cluster_f32(mapa_u32(smem_u32(&buf0[r]), tgt), v);
        }
        cluster_sync();
    }

    // ================= L2 63x500: in buf0, out -> gmem =================
    if (g < 63) {
        const float4* xf = reinterpret_cast<const float4*>(buf0);
        float s[1];
        s[0] = dot4(w2[0], xf[lane]) + dot4(w2[1], xf[lane + 32])
             + dot4(w2[2], xf[lane + 64]);
        if (lane < 29) s[0] += dot4(w2[3], xf[lane + 96]);
        warp_sumN<1>(s);
        if (lane == 0) out[g] = s[0] + b2;
    }
}

extern "C" void kernel_launch(void* const* d_in, const int* in_sizes, int n_in,
                              void* d_out, int out_size) {
    const float* inputs = (const float*)d_in[0];
    const float* W_ih   = (const float*)d_in[1];
    // d_in[2] = W_hh — dead (h0 = 0)
    const float* b_ih   = (const float*)d_in[3];
    const float* b_hh   = (const float*)d_in[4];
    const float* W_fc   = (const float*)d_in[5];
    const float* b_fc   = (const float*)d_in[6];
    const float* W_l1   = (const float*)d_in[7];
    const float* b_l1   = (const float*)d_in[8];
    const float* W_l2   = (const float*)d_in[9];
    const float* b_l2   = (const float*)d_in[10];
    float* out = (float*)d_out;

    const int dynSmem = SMEM_FLOATS * 4;     // ~110 KB
    cudaFuncSetAttribute(fused_rnn,
                         cudaFuncAttributeMaxDynamicSharedMemorySize, dynSmem);

    fused_rnn<<<NC, 512, dynSmem>>>(inputs, W_ih, b_ih, b_hh,
                                    W_fc, b_fc, W_l1, b_l1, W_l2, b_l2, out);
}